// round 14
// baseline (speedup 1.0000x reference)
#include <cuda_runtime.h>
#include <cuda_bf16.h>
#include <cstdint>

// ---------------------------------------------------------------------------
// LatticeTokenPtrNet. Round 14:
//  Encoder = R11's barrier.cluster sync (hardware barrier beat both SW
//  protocols tried in R12/R13) + R12's warp-self-contained gate layout:
//   - each warp owns 2 hidden units, all 4 gates in-warp
//   - 2-shfl chunk reduce + 4-shfl gate gather (no gate_s SMEM handoff,
//     no __syncthreads in the recurrence loop)
//   - one remote st.shared::cluster per publishing lane (8 lanes/unit)
//   - split barrier: arrive -> yout store + G prefetch -> wait
//  Everything else identical to the 2904us R11 build.
// ---------------------------------------------------------------------------

#define SEQ 1024          // T*A
#define TT  64
#define AA  16

// ------------------------- device scratch (static) -------------------------
__device__ float d_x[SEQ * 256];          // lattice embeddings
__device__ float d_G[2 * SEQ * 1024];     // gate preactivations (reused L0/L1)
__device__ float d_y[SEQ * 512];          // layer0 output (fwd|bwd)
__device__ float d_enc[SEQ * 512];        // layer1 output (fwd|bwd)
__device__ float d_Kenc[SEQ * 256];       // enc @ Wk
__device__ float d_decin[TT * 512];       // [prev_emb | tok_emb]
__device__ float d_DG0[TT * 2048];        // decin @ dWih0^T + db0
__device__ float d_H2[TT * 512];          // decoder layer-1 hidden per step
__device__ float d_q[TT * 256];           // H2 @ Wq
__device__ float d_hfin[2 * 512];         // enc final h per layer (fwd|bwd)
__device__ float d_cfin[2 * 512];         // enc final c per layer
__device__ float d_h0g[2 * 512];          // decoder layer0 h [parity][512]
__device__ float d_h1g[2 * 512];          // decoder layer1 h [parity][512]
__device__ unsigned d_barc[4];
__device__ unsigned d_barg[4];

// ------------------------------ helpers ------------------------------------
__device__ __forceinline__ float fsig(float x) {
    return 1.0f / (1.0f + __expf(-x));
}
__device__ __forceinline__ float ftanh(float x) {
    return 1.0f - 2.0f / (1.0f + __expf(2.0f * x));
}

__device__ __forceinline__ unsigned long long pack2(float x, float y) {
    unsigned long long p;
    asm("mov.b64 %0, {%1, %2};" : "=l"(p) : "f"(x), "f"(y));
    return p;
}
__device__ __forceinline__ void unpack2(unsigned long long p, float& x, float& y) {
    asm("mov.b64 {%0, %1}, %2;" : "=f"(x), "=f"(y) : "l"(p));
}
__device__ __forceinline__ unsigned long long fma2(unsigned long long a, unsigned long long b,
                                                   unsigned long long c) {
    unsigned long long d;
    asm("fma.rn.f32x2 %0, %1, %2, %3;" : "=l"(d) : "l"(a), "l"(b), "l"(c));
    return d;
}

__device__ __forceinline__ unsigned int smem_u32(const void* p) {
    unsigned int a;
    asm("{ .reg .u64 t; cvta.to.shared.u64 t, %1; cvt.u32.u64 %0, t; }"
        : "=r"(a) : "l"(p));
    return a;
}

__device__ __forceinline__ void cluster_bar() {
    asm volatile("barrier.cluster.arrive.aligned;" ::: "memory");
    asm volatile("barrier.cluster.wait.aligned;" ::: "memory");
}

// software grid barrier (decoder only); all blocks co-resident
__device__ __forceinline__ void grid_barrier(int slot, unsigned nb) {
    __syncthreads();
    if (threadIdx.x == 0) {
        volatile unsigned* genp = (volatile unsigned*)&d_barg[slot];
        unsigned g = *genp;
        __threadfence();
        unsigned old = atomicAdd(&d_barc[slot], 1u);
        if (old == nb - 1u) {
            atomicExch(&d_barc[slot], 0u);
            __threadfence();
            atomicAdd(&d_barg[slot], 1u);
        } else {
            while (*genp == g) { }
            __threadfence();
        }
    }
    __syncthreads();
}

// ------------------------------ embeddings ---------------------------------
__global__ void embed_lattice(const int* __restrict__ lattice,
                              const float* __restrict__ tab) {
    int p = blockIdx.x;            // 0..1023
    int e = threadIdx.x;           // 0..255
    int f = e >> 6, j = e & 63;
    int id = lattice[p * 4 + f];
    d_x[p * 256 + e] = tab[id * 64 + j];
}

__global__ void build_decin(const int* __restrict__ inputs,
                            const int* __restrict__ gold,
                            const int* __restrict__ sos,
                            const float* __restrict__ lat_tab,
                            const float* __restrict__ in_tab) {
    int t = blockIdx.x;            // 0..63
    int e = threadIdx.x;           // 0..255
    float prev;
    if (t == 0) {
        prev = lat_tab[sos[e >> 6] * 64 + (e & 63)];
    } else {
        int g = gold[t - 1];
        prev = d_x[((t - 1) * AA + g) * 256 + e];
    }
    d_decin[t * 512 + e] = prev;
    d_decin[t * 512 + 256 + e] = in_tab[inputs[t] * 256 + e];
}

// ------------------------------ GEMMs --------------------------------------
// C[M,N] = A[M,K] @ B[N,K]^T + bias[N]; 128x128 tile, 8x8/thread, batched z.
__global__ void __launch_bounds__(256) gemm_tn128(
    const float* __restrict__ A, const float* __restrict__ B,
    const float* __restrict__ bias, float* __restrict__ C,
    int M, int N, int K, int sB, int sC, int sBias)
{
    int z = blockIdx.z;
    B += (size_t)z * sB;
    C += (size_t)z * sC;
    const float* bz = bias + (size_t)z * sBias;
    __shared__ float As[16][132];
    __shared__ float Bs[16][132];
    int tid = threadIdx.x;
    int tx = tid & 15, ty = tid >> 4;
    int row0 = blockIdx.y << 7, col0 = blockIdx.x << 7;
    float acc[8][8];
#pragma unroll
    for (int i = 0; i < 8; i++)
#pragma unroll
        for (int j = 0; j < 8; j++) acc[i][j] = 0.f;

    for (int kt = 0; kt < K; kt += 16) {
#pragma unroll
        for (int it = 0; it < 2; it++) {
            int idx = tid * 2 + it;            // 0..511
            int m = idx >> 2;                  // 0..127
            int q = (idx & 3) << 2;            // 0,4,8,12
            int rr = row0 + m; if (rr >= M) rr = M - 1;
            float4 v = *(const float4*)&A[(size_t)rr * K + kt + q];
            As[q][m] = v.x; As[q + 1][m] = v.y; As[q + 2][m] = v.z; As[q + 3][m] = v.w;
            float4 u = *(const float4*)&B[(size_t)(col0 + m) * K + kt + q];
            Bs[q][m] = u.x; Bs[q + 1][m] = u.y; Bs[q + 2][m] = u.z; Bs[q + 3][m] = u.w;
        }
        __syncthreads();
#pragma unroll
        for (int k = 0; k < 16; k++) {
            float av[8], bv[8];
            *(float4*)&av[0] = *(const float4*)&As[k][ty * 8];
            *(float4*)&av[4] = *(const float4*)&As[k][ty * 8 + 4];
            *(float4*)&bv[0] = *(const float4*)&Bs[k][tx * 8];
            *(float4*)&bv[4] = *(const float4*)&Bs[k][tx * 8 + 4];
#pragma unroll
            for (int i = 0; i < 8; i++)
#pragma unroll
                for (int j = 0; j < 8; j++) acc[i][j] += av[i] * bv[j];
        }
        __syncthreads();
    }
#pragma unroll
    for (int i = 0; i < 8; i++) {
        int r = row0 + ty * 8 + i;
        if (r < M) {
#pragma unroll
            for (int j = 0; j < 8; j += 4) {
                int cix = col0 + tx * 8 + j;
                float4 o;
                o.x = acc[i][j]     + bz[cix];
                o.y = acc[i][j + 1] + bz[cix + 1];
                o.z = acc[i][j + 2] + bz[cix + 2];
                o.w = acc[i][j + 3] + bz[cix + 3];
                *(float4*)&C[(size_t)r * N + cix] = o;
            }
        }
    }
}

// C[M,N] = A[M,K] @ B[K,N]   (no bias) - small epilogue GEMMs
__global__ void __launch_bounds__(256) gemm_nn(
    const float* __restrict__ A, const float* __restrict__ B,
    float* __restrict__ C, int M, int N, int K)
{
    __shared__ float As[16][65];
    __shared__ float Bs[16][65];
    int tid = threadIdx.x;
    int tx = tid & 15, ty = tid >> 4;
    int row0 = blockIdx.y << 6, col0 = blockIdx.x << 6;
    float acc[4][4];
#pragma unroll
    for (int i = 0; i < 4; i++)
#pragma unroll
        for (int j = 0; j < 4; j++) acc[i][j] = 0.f;
    for (int kt = 0; kt < K; kt += 16) {
#pragma unroll
        for (int i = 0; i < 4; i++) {
            int idx = tid + (i << 8);
            int m = idx >> 4, k = idx & 15;
            As[k][m] = A[(size_t)(row0 + m) * K + kt + k];
            int kk = idx >> 6, n = idx & 63;
            Bs[kk][n] = B[(size_t)(kt + kk) * N + col0 + n];
        }
        __syncthreads();
#pragma unroll
        for (int k = 0; k < 16; k++) {
            float a0[4], b0[4];
#pragma unroll
            for (int i = 0; i < 4; i++) { a0[i] = As[k][(ty << 2) + i]; b0[i] = Bs[k][(tx << 2) + i]; }
#pragma unroll
            for (int i = 0; i < 4; i++)
#pragma unroll
                for (int j = 0; j < 4; j++) acc[i][j] += a0[i] * b0[j];
        }
        __syncthreads();
    }
#pragma unroll
    for (int i = 0; i < 4; i++) {
        int r = row0 + (ty << 2) + i;
#pragma unroll
        for (int j = 0; j < 4; j++) {
            C[(size_t)r * N + col0 + (tx << 2) + j] = acc[i][j];
        }
    }
}

// --------------------------- encoder recurrence (cluster) ------------------
// grid = 16 CTAs, cluster (8,1,1): blocks 0-7 = forward dir, 8-15 = backward.
// CTA rank r owns 32 hidden units; warp w owns units {2w, 2w+1} with all 4
// gates self-contained: lane l -> row_local (l>>2) = gate*2 + unit-parity,
// 64-col chunk (l&3). 2-shfl chunk reduce + 4-shfl gate gather, redundant
// pointwise in 16 lanes/unit. Sync = split barrier.cluster: publish h via
// one st.shared::cluster per lane (k<8), arrive, overlap yout store +
// G prefetch, wait at top of next step.
__global__ void __launch_bounds__(512, 1) __cluster_dims__(8, 1, 1)
enc_recur_cl(const float* __restrict__ Whh,   // [2][1024][256]
             float* __restrict__ yout,        // [1024][512]
             int layer)
{
    __shared__ __align__(16) float h_buf[2][256];

    int tid = threadIdx.x;
    int w = tid >> 5, l = tid & 31;
    int dir = blockIdx.x >> 3;
    int rank = blockIdx.x & 7;

    const float* Wd = Whh + (size_t)dir * 1024 * 256;
    const float* Gd = d_G + (size_t)dir * SEQ * 1024;

    int rl = l >> 2;                 // row_local 0..7 = gate*2 + unit parity
    int g  = rl >> 1;                // gate 0..3 (i,f,g,o)
    int p  = rl & 1;                 // unit parity within warp
    int chunk = l & 3;               // 64-col chunk
    int grow = g * 256 + rank * 32 + 2 * w + p;   // gate row in [0,1024)
    int unit = rank * 32 + 2 * w + p;             // hidden unit index in dir
    int k = ((l >> 3) << 2) + (l & 3);            // 0..15 among unit's lanes

    // 64 weight floats for (row grow, cols chunk*64..chunk*64+63) as f32x2
    unsigned long long wreg[32];
    {
        const float* wp = &Wd[(size_t)grow * 256 + chunk * 64];
#pragma unroll
        for (int i = 0; i < 16; i++) {
            float4 v4 = *(const float4*)&wp[i * 4];
            wreg[2 * i]     = pack2(v4.x, v4.y);
            wreg[2 * i + 1] = pack2(v4.z, v4.w);
        }
    }

    if (tid < 256) h_buf[0][tid] = 0.f;
    unsigned int hb = smem_u32(&h_buf[0][0]);
    cluster_bar();    // h_buf[0] zero visible cluster-wide

    float c_reg = 0.f;
    float gcur = __ldg(&Gd[(size_t)(dir ? 1023 : 0) * 1024 + grow]);

    for (int s = 0; s < 1024; s++) {
        int par = s & 1;
        if (s) {   // pairs with arrive at end of step s-1
            asm volatile("barrier.cluster.wait.aligned;" ::: "memory");
        }
        // prefetch next step's gate preactivation (hidden under matvec)
        float gnext = 0.f;
        if (s < 1023) {
            int pos1 = dir ? (1022 - s) : (s + 1);
            gnext = __ldg(&Gd[(size_t)pos1 * 1024 + grow]);
        }
        int pos = dir ? (1023 - s) : s;

        // matvec: this lane's gate row over its 64-col chunk
        const float* hp = &h_buf[par][chunk * 64];
        unsigned long long a0 = 0ull, a1 = 0ull, a2 = 0ull, a3 = 0ull;
#pragma unroll
        for (int i = 0; i < 8; i++) {
            ulonglong2 h0 = *(const ulonglong2*)&hp[i * 8];
            ulonglong2 h1 = *(const ulonglong2*)&hp[i * 8 + 4];
            a0 = fma2(wreg[4 * i],     h0.x, a0);
            a1 = fma2(wreg[4 * i + 1], h0.y, a1);
            a2 = fma2(wreg[4 * i + 2], h1.x, a2);
            a3 = fma2(wreg[4 * i + 3], h1.y, a3);
        }
        float x0, x1, y0, y1, z0, z1, u0, u1;
        unpack2(a0, x0, x1); unpack2(a1, y0, y1);
        unpack2(a2, z0, z1); unpack2(a3, u0, u1);
        float v = (x0 + x1) + (y0 + y1) + ((z0 + z1) + (u0 + u1));
        // reduce over the 4 chunk lanes of this row
        v += __shfl_xor_sync(0xffffffffu, v, 1);
        v += __shfl_xor_sync(0xffffffffu, v, 2);
        v += gcur;
        gcur = gnext;

        // gather the 4 gates of this lane's unit (gate G lives at lane 8G+bl)
        int bl = 4 * p + (l & 3);
        float gi = __shfl_sync(0xffffffffu, v, bl);
        float gf = __shfl_sync(0xffffffffu, v, 8 + bl);
        float gg = __shfl_sync(0xffffffffu, v, 16 + bl);
        float go = __shfl_sync(0xffffffffu, v, 24 + bl);

        c_reg = fsig(gf) * c_reg + fsig(gi) * ftanh(gg);
        float h = fsig(go) * ftanh(c_reg);

        if (s < 1023) {
            if (k < 8) {   // one remote store per lane: peer k's buf[par^1][unit]
                unsigned int base = hb
                    + ((((unsigned)(par ^ 1)) << 8) + (unsigned)unit) * 4u;
                unsigned int ra;
                asm volatile("mapa.shared::cluster.u32 %0, %1, %2;"
                             : "=r"(ra) : "r"(base), "r"(k));
                asm volatile("st.shared::cluster.f32 [%0], %1;"
                             :: "r"(ra), "f"(h) : "memory");
            }
            // release the h stores; peers' wait at next step acquires them
            asm volatile("barrier.cluster.arrive.aligned;" ::: "memory");
        }
        // overlap with peer arrival skew: global output store
        if (k == 8) {
            yout[(size_t)pos * 512 + (dir << 8) + unit] = h;
            if (s == 1023) {
                d_hfin[layer * 512 + (dir << 8) + unit] = h;
                d_cfin[layer * 512 + (dir << 8) + unit] = c_reg;
            }
        }
    }
    cluster_bar();   // no CTA exits while peers could still touch its SMEM
}

// ----------------------- decoder recurrence (pipelined) --------------------
// 96 blocks x 512 threads. Blocks [0,32): cell0, 16 units each (64 gate rows
// x 512 cols). Blocks [32,96): cell1, 8 units each (32 gate rows x 1024 cols).
// Phase p: cell0 computes step p (p<64), cell1 computes step p-1 (p>=1).
__global__ void __launch_bounds__(512, 1) dec_recur_p(
    const float* __restrict__ dWih, const float* __restrict__ dWhh,
    const float* __restrict__ db)
{
    extern __shared__ float sm[];
    float* ws = sm;                    // 32768 floats (128KB)
    float* xc = sm + 32768;            // 1024
    float* gate_s = xc + 1024;         // 64

    int b = blockIdx.x, tid = threadIdx.x;
    int w = tid >> 5, l = tid & 31;

    if (b < 32) {
        // ---------------- cell 0 ----------------
        int ub = b * 16;
        for (int idx = tid; idx < 64 * 512; idx += 512) {
            int r = idx >> 9, k = idx & 511;
            int gr = (r >> 4) * 512 + ub + (r & 15);
            ws[idx] = dWhh[(size_t)gr * 512 + k];
        }
        float c0 = 0.f;
        if (tid < 16) {
            int ug = ub + tid;
            c0 = d_cfin[ug];
            d_h0g[ug] = d_hfin[ug];               // parity 0 init
        }
        __threadfence();
        grid_barrier(2, 96);

        bool writer = ((l & 7) == 0);
        int wrow = w * 4 + (l >> 3);
        int wgrow = (wrow >> 4) * 512 + ub + (wrow & 15);

        for (int p = 0; p < 65; p++) {
            int par = p & 1;
            if (p < 64) {
                float pre = 0.f;
                if (writer) pre = __ldcg(&d_DG0[(size_t)p * 2048 + wgrow]);
                xc[tid] = __ldcg(&d_h0g[par * 512 + tid]);
                __syncthreads();
                ulonglong2 xv[4];
#pragma unroll
                for (int q = 0; q < 4; q++)
                    xv[q] = *(const ulonglong2*)&xc[(q * 32 + l) * 4];
                float a[4];
#pragma unroll
                for (int r = 0; r < 4; r++) {
                    const float* wrp = &ws[(w * 4 + r) * 512];
                    unsigned long long acc = 0ull;
#pragma unroll
                    for (int q = 0; q < 4; q++) {
                        ulonglong2 wv = *(const ulonglong2*)&wrp[(q * 32 + l) * 4];
                        acc = fma2(wv.x, xv[q].x, acc);
                        acc = fma2(wv.y, xv[q].y, acc);
                    }
                    float lo, hi; unpack2(acc, lo, hi);
                    a[r] = lo + hi;
                }
#pragma unroll
                for (int i = 0; i < 2; i++) {
                    float give = (l & 16) ? a[i] : a[i + 2];
                    float keep = (l & 16) ? a[i + 2] : a[i];
                    a[i] = keep + __shfl_xor_sync(0xffffffffu, give, 16);
                }
                {
                    float give = (l & 8) ? a[0] : a[1];
                    float keep = (l & 8) ? a[1] : a[0];
                    a[0] = keep + __shfl_xor_sync(0xffffffffu, give, 8);
                }
                a[0] += __shfl_xor_sync(0xffffffffu, a[0], 4);
                a[0] += __shfl_xor_sync(0xffffffffu, a[0], 2);
                a[0] += __shfl_xor_sync(0xffffffffu, a[0], 1);
                if (writer) gate_s[wrow] = a[0] + pre;
                __syncthreads();
                if (tid < 16) {
                    int u = tid;
                    float gi = gate_s[u], gf = gate_s[16 + u];
                    float gg = gate_s[32 + u], go = gate_s[48 + u];
                    c0 = fsig(gf) * c0 + fsig(gi) * ftanh(gg);
                    float h = fsig(go) * ftanh(c0);
                    d_h0g[(par ^ 1) * 512 + ub + u] = h;
                }
            }
            __threadfence();
            grid_barrier(2, 96);
        }
    } else {
        // ---------------- cell 1 ----------------
        int bi = b - 32;
        int ub = bi * 8;
        for (int idx = tid; idx < 32 * 1024; idx += 512) {
            int r = idx >> 10, k = idx & 1023;
            int gr = (r >> 3) * 512 + ub + (r & 7);
            float v = (k < 512)
                ? dWih[(size_t)2048 * 512 + (size_t)gr * 512 + k]
                : dWhh[(size_t)2048 * 512 + (size_t)gr * 512 + (k - 512)];
            ws[r * 1024 + k] = v;
        }
        float c1 = 0.f;
        if (tid < 8) {
            int ug = ub + tid;
            c1 = d_cfin[512 + ug];
            d_h1g[512 + ug] = d_hfin[512 + ug];   // parity 1 init (first read p=1)
        }
        __threadfence();
        grid_barrier(2, 96);

        bool writer = ((l & 15) == 0);
        int wrow = w * 2 + (l >> 4);
        int wgrow = (wrow >> 3) * 512 + ub + (wrow & 7);
        float b1r = 0.f;
        if (writer) b1r = db[2048 + wgrow];

        for (int p = 0; p < 65; p++) {
            int par = p & 1;
            if (p >= 1) {
                int t = p - 1;
                xc[tid] = __ldcg(&d_h0g[par * 512 + tid]);
                xc[512 + tid] = __ldcg(&d_h1g[par * 512 + tid]);
                __syncthreads();
                ulonglong2 xv[8];
#pragma unroll
                for (int q = 0; q < 8; q++)
                    xv[q] = *(const ulonglong2*)&xc[(q * 32 + l) * 4];
                float a[2];
#pragma unroll
                for (int r = 0; r < 2; r++) {
                    const float* wrp = &ws[(w * 2 + r) * 1024];
                    unsigned long long acc = 0ull;
#pragma unroll
                    for (int q = 0; q < 8; q++) {
                        ulonglong2 wv = *(const ulonglong2*)&wrp[(q * 32 + l) * 4];
                        acc = fma2(wv.x, xv[q].x, acc);
                        acc = fma2(wv.y, xv[q].y, acc);
                    }
                    float lo, hi; unpack2(acc, lo, hi);
                    a[r] = lo + hi;
                }
                {
                    float give = (l & 16) ? a[0] : a[1];
                    float keep = (l & 16) ? a[1] : a[0];
                    a[0] = keep + __shfl_xor_sync(0xffffffffu, give, 16);
                }
                a[0] += __shfl_xor_sync(0xffffffffu, a[0], 8);
                a[0] += __shfl_xor_sync(0xffffffffu, a[0], 4);
                a[0] += __shfl_xor_sync(0xffffffffu, a[0], 2);
                a[0] += __shfl_xor_sync(0xffffffffu, a[0], 1);
                if (writer) gate_s[wrow] = a[0] + b1r;
                __syncthreads();
                if (tid < 8) {
                    int u = tid;
                    float gi = gate_s[u], gf = gate_s[8 + u];
                    float gg = gate_s[16 + u], go = gate_s[24 + u];
                    c1 = fsig(gf) * c1 + fsig(gi) * ftanh(gg);
                    float h = fsig(go) * ftanh(c1);
                    d_h1g[(par ^ 1) * 512 + ub + u] = h;
                    d_H2[(size_t)t * 512 + ub + u] = h;
                }
            }
            __threadfence();
            grid_barrier(2, 96);
        }
    }
}

// ------------------------------ scores -------------------------------------
__global__ void scores_kernel(const float* __restrict__ v,
                              const int* __restrict__ alens,
                              float* __restrict__ out)
{
    int t = blockIdx.x;
    int a = threadIdx.x >> 5;
    int lane = threadIdx.x & 31;
    const float* Kp = &d_Kenc[(size_t)(t * AA + a) * 256];
    const float* qp = &d_q[(size_t)t * 256];
    float s = 0.f;
#pragma unroll
    for (int i = 0; i < 8; i++) {
        int d = lane + (i << 5);
        s += tanhf(Kp[d] + qp[d]) * v[d];
    }
    s += __shfl_down_sync(0xffffffffu, s, 16);
    s += __shfl_down_sync(0xffffffffu, s, 8);
    s += __shfl_down_sync(0xffffffffu, s, 4);
    s += __shfl_down_sync(0xffffffffu, s, 2);
    s += __shfl_down_sync(0xffffffffu, s, 1);
    if (lane == 0) out[t * AA + a] = (a < alens[t]) ? s : -1e10f;
}

// ------------------------------ launcher -----------------------------------
extern "C" void kernel_launch(void* const* d_in, const int* in_sizes, int n_in,
                              void* d_out, int out_size)
{
    (void)in_sizes; (void)n_in; (void)out_size;
    const int*   lattice = (const int*)d_in[0];
    const int*   alens   = (const int*)d_in[1];
    const int*   inputs  = (const int*)d_in[2];
    const int*   gold    = (const int*)d_in[4];
    const int*   sos     = (const int*)d_in[5];
    const float* lat_tab = (const float*)d_in[6];
    const float* in_tab  = (const float*)d_in[7];
    const float* eWih0   = (const float*)d_in[8];
    const float* eWhh0   = (const float*)d_in[9];
    const float* eb0     = (const float*)d_in[10];
    const float* eWih1   = (const float*)d_in[11];
    const float* eWhh1   = (const float*)d_in[12];
    const float* eb1     = (const float*)d_in[13];
    const float* dWih    = (const float*)d_in[14];
    const float* dWhh    = (const float*)d_in[15];
    const float* db      = (const float*)d_in[16];
    const float* Wq      = (const float*)d_in[17];
    const float* Wk      = (const float*)d_in[18];
    const float* av      = (const float*)d_in[19];
    float* out = (float*)d_out;

    float *px, *py, *penc, *pG, *pK, *pdecin, *pDG0, *pH2, *pq;
    cudaGetSymbolAddress((void**)&px,    d_x);
    cudaGetSymbolAddress((void**)&py,    d_y);
    cudaGetSymbolAddress((void**)&penc,  d_enc);
    cudaGetSymbolAddress((void**)&pG,    d_G);
    cudaGetSymbolAddress((void**)&pK,    d_Kenc);
    cudaGetSymbolAddress((void**)&pdecin,d_decin);
    cudaGetSymbolAddress((void**)&pDG0,  d_DG0);
    cudaGetSymbolAddress((void**)&pH2,   d_H2);
    cudaGetSymbolAddress((void**)&pq,    d_q);

    const int DEC_SMEM = (32768 + 1024 + 64) * (int)sizeof(float);
    cudaFuncSetAttribute(dec_recur_p, cudaFuncAttributeMaxDynamicSharedMemorySize, DEC_SMEM);

    // 1. embeddings + decoder inputs
    embed_lattice<<<SEQ, 256>>>(lattice, lat_tab);
    build_decin<<<TT, 256>>>(inputs, gold, sos, lat_tab, in_tab);

    // 2. layer-0 gate preactivations
    gemm_tn128<<<dim3(8, 8, 2), 256>>>(px, eWih0, eb0, pG,
                                       SEQ, 1024, 256, 1024 * 256, SEQ * 1024, 1024);
    // 3. layer-0 recurrence (two independent 8-CTA clusters: fwd + bwd)
    enc_recur_cl<<<16, 512>>>(eWhh0, py, 0);
    // 4. layer-1 gate preactivations
    gemm_tn128<<<dim3(8, 8, 2), 256>>>(py, eWih1, eb1, pG,
                                       SEQ, 1024, 512, 1024 * 512, SEQ * 1024, 1024);
    // 5. layer-1 recurrence
    enc_recur_cl<<<16, 512>>>(eWhh1, penc, 1);
    // 6. attention keys + decoder layer-0 input preactivations
    gemm_nn<<<dim3(4, 16), 256>>>(penc, Wk, pK, SEQ, 256, 512);
    gemm_tn128<<<dim3(16, 1, 1), 256>>>(pdecin, dWih, db, pDG0,
                                        TT, 2048, 512, 0, 0, 0);
    // 7. decoder recurrence (pipelined: cell0 step t || cell1 step t-1)
    dec_recur_p<<<96, 512, DEC_SMEM>>>(dWih, dWhh, db);
    // 8. attention queries + scores
    gemm_nn<<<dim3(4, 1), 256>>>(pH2, Wq, pq, TT, 256, 512);
    scores_kernel<<<TT, 512>>>(av, alens, out);
}

// round 15
// speedup vs baseline: 2.4251x; 2.4251x over previous
#include <cuda_runtime.h>
#include <cuda_bf16.h>
#include <cstdint>

// ---------------------------------------------------------------------------
// LatticeTokenPtrNet. Round 15 = Round 11 (2904us, best) + confined encoder
// tweaks. R12/R14 post-mortem: the 1-row-per-lane layout removed all h
// register reuse (128KB LDS/step vs 16KB) and was LDS-bound - reverted to
// R11's 8-rows-per-lane matvec. Changes vs R11, encoder only:
//  1. split barrier.cluster: arrive after publish, wait at top of next step
//  2. pointwise+publish parallelized over warps 0-3 (4 lanes/unit,
//     2 remote stores/lane) instead of warp0 alone (8 serial stores/lane)
//  3. d_G gate preactivation double-buffered one step ahead
// ---------------------------------------------------------------------------

#define SEQ 1024          // T*A
#define TT  64
#define AA  16

// ------------------------- device scratch (static) -------------------------
__device__ float d_x[SEQ * 256];          // lattice embeddings
__device__ float d_G[2 * SEQ * 1024];     // gate preactivations (reused L0/L1)
__device__ float d_y[SEQ * 512];          // layer0 output (fwd|bwd)
__device__ float d_enc[SEQ * 512];        // layer1 output (fwd|bwd)
__device__ float d_Kenc[SEQ * 256];       // enc @ Wk
__device__ float d_decin[TT * 512];       // [prev_emb | tok_emb]
__device__ float d_DG0[TT * 2048];        // decin @ dWih0^T + db0
__device__ float d_H2[TT * 512];          // decoder layer-1 hidden per step
__device__ float d_q[TT * 256];           // H2 @ Wq
__device__ float d_hfin[2 * 512];         // enc final h per layer (fwd|bwd)
__device__ float d_cfin[2 * 512];         // enc final c per layer
__device__ float d_h0g[2 * 512];          // decoder layer0 h [parity][512]
__device__ float d_h1g[2 * 512];          // decoder layer1 h [parity][512]
__device__ unsigned d_barc[4];
__device__ unsigned d_barg[4];

// ------------------------------ helpers ------------------------------------
__device__ __forceinline__ float fsig(float x) {
    return 1.0f / (1.0f + __expf(-x));
}
__device__ __forceinline__ float ftanh(float x) {
    return 1.0f - 2.0f / (1.0f + __expf(2.0f * x));
}

__device__ __forceinline__ unsigned long long pack2(float x, float y) {
    unsigned long long p;
    asm("mov.b64 %0, {%1, %2};" : "=l"(p) : "f"(x), "f"(y));
    return p;
}
__device__ __forceinline__ void unpack2(unsigned long long p, float& x, float& y) {
    asm("mov.b64 {%0, %1}, %2;" : "=f"(x), "=f"(y) : "l"(p));
}
__device__ __forceinline__ unsigned long long fma2(unsigned long long a, unsigned long long b,
                                                   unsigned long long c) {
    unsigned long long d;
    asm("fma.rn.f32x2 %0, %1, %2, %3;" : "=l"(d) : "l"(a), "l"(b), "l"(c));
    return d;
}

__device__ __forceinline__ unsigned int smem_u32(const void* p) {
    unsigned int a;
    asm("{ .reg .u64 t; cvta.to.shared.u64 t, %1; cvt.u32.u64 %0, t; }"
        : "=r"(a) : "l"(p));
    return a;
}

__device__ __forceinline__ void cluster_bar() {
    asm volatile("barrier.cluster.arrive.aligned;" ::: "memory");
    asm volatile("barrier.cluster.wait.aligned;" ::: "memory");
}

// software grid barrier (decoder only); all blocks co-resident
__device__ __forceinline__ void grid_barrier(int slot, unsigned nb) {
    __syncthreads();
    if (threadIdx.x == 0) {
        volatile unsigned* genp = (volatile unsigned*)&d_barg[slot];
        unsigned g = *genp;
        __threadfence();
        unsigned old = atomicAdd(&d_barc[slot], 1u);
        if (old == nb - 1u) {
            atomicExch(&d_barc[slot], 0u);
            __threadfence();
            atomicAdd(&d_barg[slot], 1u);
        } else {
            while (*genp == g) { }
            __threadfence();
        }
    }
    __syncthreads();
}

// ------------------------------ embeddings ---------------------------------
__global__ void embed_lattice(const int* __restrict__ lattice,
                              const float* __restrict__ tab) {
    int p = blockIdx.x;            // 0..1023
    int e = threadIdx.x;           // 0..255
    int f = e >> 6, j = e & 63;
    int id = lattice[p * 4 + f];
    d_x[p * 256 + e] = tab[id * 64 + j];
}

__global__ void build_decin(const int* __restrict__ inputs,
                            const int* __restrict__ gold,
                            const int* __restrict__ sos,
                            const float* __restrict__ lat_tab,
                            const float* __restrict__ in_tab) {
    int t = blockIdx.x;            // 0..63
    int e = threadIdx.x;           // 0..255
    float prev;
    if (t == 0) {
        prev = lat_tab[sos[e >> 6] * 64 + (e & 63)];
    } else {
        int g = gold[t - 1];
        prev = d_x[((t - 1) * AA + g) * 256 + e];
    }
    d_decin[t * 512 + e] = prev;
    d_decin[t * 512 + 256 + e] = in_tab[inputs[t] * 256 + e];
}

// ------------------------------ GEMMs --------------------------------------
// C[M,N] = A[M,K] @ B[N,K]^T + bias[N]; 128x128 tile, 8x8/thread, batched z.
__global__ void __launch_bounds__(256) gemm_tn128(
    const float* __restrict__ A, const float* __restrict__ B,
    const float* __restrict__ bias, float* __restrict__ C,
    int M, int N, int K, int sB, int sC, int sBias)
{
    int z = blockIdx.z;
    B += (size_t)z * sB;
    C += (size_t)z * sC;
    const float* bz = bias + (size_t)z * sBias;
    __shared__ float As[16][132];
    __shared__ float Bs[16][132];
    int tid = threadIdx.x;
    int tx = tid & 15, ty = tid >> 4;
    int row0 = blockIdx.y << 7, col0 = blockIdx.x << 7;
    float acc[8][8];
#pragma unroll
    for (int i = 0; i < 8; i++)
#pragma unroll
        for (int j = 0; j < 8; j++) acc[i][j] = 0.f;

    for (int kt = 0; kt < K; kt += 16) {
#pragma unroll
        for (int it = 0; it < 2; it++) {
            int idx = tid * 2 + it;            // 0..511
            int m = idx >> 2;                  // 0..127
            int q = (idx & 3) << 2;            // 0,4,8,12
            int rr = row0 + m; if (rr >= M) rr = M - 1;
            float4 v = *(const float4*)&A[(size_t)rr * K + kt + q];
            As[q][m] = v.x; As[q + 1][m] = v.y; As[q + 2][m] = v.z; As[q + 3][m] = v.w;
            float4 u = *(const float4*)&B[(size_t)(col0 + m) * K + kt + q];
            Bs[q][m] = u.x; Bs[q + 1][m] = u.y; Bs[q + 2][m] = u.z; Bs[q + 3][m] = u.w;
        }
        __syncthreads();
#pragma unroll
        for (int k = 0; k < 16; k++) {
            float av[8], bv[8];
            *(float4*)&av[0] = *(const float4*)&As[k][ty * 8];
            *(float4*)&av[4] = *(const float4*)&As[k][ty * 8 + 4];
            *(float4*)&bv[0] = *(const float4*)&Bs[k][tx * 8];
            *(float4*)&bv[4] = *(const float4*)&Bs[k][tx * 8 + 4];
#pragma unroll
            for (int i = 0; i < 8; i++)
#pragma unroll
                for (int j = 0; j < 8; j++) acc[i][j] += av[i] * bv[j];
        }
        __syncthreads();
    }
#pragma unroll
    for (int i = 0; i < 8; i++) {
        int r = row0 + ty * 8 + i;
        if (r < M) {
#pragma unroll
            for (int j = 0; j < 8; j += 4) {
                int cix = col0 + tx * 8 + j;
                float4 o;
                o.x = acc[i][j]     + bz[cix];
                o.y = acc[i][j + 1] + bz[cix + 1];
                o.z = acc[i][j + 2] + bz[cix + 2];
                o.w = acc[i][j + 3] + bz[cix + 3];
                *(float4*)&C[(size_t)r * N + cix] = o;
            }
        }
    }
}

// C[M,N] = A[M,K] @ B[K,N]   (no bias) - small epilogue GEMMs
__global__ void __launch_bounds__(256) gemm_nn(
    const float* __restrict__ A, const float* __restrict__ B,
    float* __restrict__ C, int M, int N, int K)
{
    __shared__ float As[16][65];
    __shared__ float Bs[16][65];
    int tid = threadIdx.x;
    int tx = tid & 15, ty = tid >> 4;
    int row0 = blockIdx.y << 6, col0 = blockIdx.x << 6;
    float acc[4][4];
#pragma unroll
    for (int i = 0; i < 4; i++)
#pragma unroll
        for (int j = 0; j < 4; j++) acc[i][j] = 0.f;
    for (int kt = 0; kt < K; kt += 16) {
#pragma unroll
        for (int i = 0; i < 4; i++) {
            int idx = tid + (i << 8);
            int m = idx >> 4, k = idx & 15;
            As[k][m] = A[(size_t)(row0 + m) * K + kt + k];
            int kk = idx >> 6, n = idx & 63;
            Bs[kk][n] = B[(size_t)(kt + kk) * N + col0 + n];
        }
        __syncthreads();
#pragma unroll
        for (int k = 0; k < 16; k++) {
            float a0[4], b0[4];
#pragma unroll
            for (int i = 0; i < 4; i++) { a0[i] = As[k][(ty << 2) + i]; b0[i] = Bs[k][(tx << 2) + i]; }
#pragma unroll
            for (int i = 0; i < 4; i++)
#pragma unroll
                for (int j = 0; j < 4; j++) acc[i][j] += a0[i] * b0[j];
        }
        __syncthreads();
    }
#pragma unroll
    for (int i = 0; i < 4; i++) {
        int r = row0 + (ty << 2) + i;
#pragma unroll
        for (int j = 0; j < 4; j++) {
            C[(size_t)r * N + col0 + (tx << 2) + j] = acc[i][j];
        }
    }
}

// --------------------------- encoder recurrence (cluster) ------------------
// grid = 16 CTAs, cluster (8,1,1): blocks 0-7 = forward dir, 8-15 = backward.
// CTA rank r owns 32 hidden units = 128 gate rows x 256 cols; weights in
// registers as f32x2 pairs, 8 rows/lane (8x h reuse - load-bearing, see
// R12/R14 post-mortem). Per step: matvec, shfl halving reduce, gate_s STS,
// __syncthreads, pointwise in warps 0-3 (4 lanes/unit, 2 remote stores/lane),
// split barrier.cluster arrive -> yout overlap -> wait at next step top.
__global__ void __launch_bounds__(512, 1) __cluster_dims__(8, 1, 1)
enc_recur_cl(const float* __restrict__ Whh,   // [2][1024][256]
             float* __restrict__ yout,        // [1024][512]
             int layer)
{
    __shared__ __align__(16) float h_buf[2][256];
    __shared__ float gate_s[128];

    int tid = threadIdx.x;
    int w = tid >> 5, l = tid & 31;
    int dir = blockIdx.x >> 3;
    int rank = blockIdx.x & 7;

    const float* Wd = Whh + (size_t)dir * 1024 * 256;
    const float* Gd = d_G + (size_t)dir * SEQ * 1024;

    // weight registers as f32x2 pairs: rows lr=8w+i, col pairs
    // {4l..4l+3, 128+4l..128+4l+3}
    unsigned long long wr2[8][4];
#pragma unroll
    for (int i = 0; i < 8; i++) {
        int lr = w * 8 + i;
        int gr = ((lr >> 5) << 8) + rank * 32 + (lr & 31);
        const float* wp = &Wd[(size_t)gr * 256];
        float4 a4 = *(const float4*)&wp[4 * l];
        float4 b4 = *(const float4*)&wp[128 + 4 * l];
        wr2[i][0] = pack2(a4.x, a4.y);
        wr2[i][1] = pack2(a4.z, a4.w);
        wr2[i][2] = pack2(b4.x, b4.y);
        wr2[i][3] = pack2(b4.z, b4.w);
    }
    bool writer = ((l & 3) == 0);
    int wrow = w * 8 + (l >> 2);
    int wgrow = ((wrow >> 5) << 8) + rank * 32 + (wrow & 31);

    // pointwise assignment: warps 0-3, 4 lanes per unit
    bool pw = (tid < 128);
    int punit = w * 8 + (l >> 2);                 // 0..31 (valid for pw)
    int unit = rank * 32 + punit;                 // global unit in dir
    int k2 = (l & 3) * 2;                         // this lane's 2 peer ranks
    bool lead = ((l & 3) == 0);                   // yout/final writer lane

    if (tid < 256) h_buf[0][tid] = 0.f;
    unsigned int hb = smem_u32(&h_buf[0][0]);
    cluster_bar();    // h_buf[0] zero visible cluster-wide

    float c_reg = 0.f;
    float gcur = 0.f;
    if (writer) gcur = __ldg(&Gd[(size_t)(dir ? 1023 : 0) * 1024 + wgrow]);

    for (int s = 0; s < 1024; s++) {
        int par = s & 1;
        if (s) {   // pairs with arrive at end of step s-1
            asm volatile("barrier.cluster.wait.aligned;" ::: "memory");
        }
        // prefetch next step's gate preactivation (hidden under matvec)
        float gnext = 0.f;
        if (writer && s < 1023) {
            int pos1 = dir ? (1022 - s) : (s + 1);
            gnext = __ldg(&Gd[(size_t)pos1 * 1024 + wgrow]);
        }
        int pos = dir ? (1023 - s) : s;

        ulonglong2 hA = *(const ulonglong2*)&h_buf[par][4 * l];
        ulonglong2 hB = *(const ulonglong2*)&h_buf[par][128 + 4 * l];

        float a[8];
#pragma unroll
        for (int i = 0; i < 8; i++) {
            unsigned long long acc = fma2(wr2[i][0], hA.x, 0ull);
            acc = fma2(wr2[i][1], hA.y, acc);
            acc = fma2(wr2[i][2], hB.x, acc);
            acc = fma2(wr2[i][3], hB.y, acc);
            float lo, hi; unpack2(acc, lo, hi);
            a[i] = lo + hi;
        }
        // halving reduction across 32 lanes: 8 accs -> 1, rows redistributed
#pragma unroll
        for (int i = 0; i < 4; i++) {
            float give = (l & 16) ? a[i] : a[i + 4];
            float keep = (l & 16) ? a[i + 4] : a[i];
            a[i] = keep + __shfl_xor_sync(0xffffffffu, give, 16);
        }
#pragma unroll
        for (int i = 0; i < 2; i++) {
            float give = (l & 8) ? a[i] : a[i + 2];
            float keep = (l & 8) ? a[i + 2] : a[i];
            a[i] = keep + __shfl_xor_sync(0xffffffffu, give, 8);
        }
        {
            float give = (l & 4) ? a[0] : a[1];
            float keep = (l & 4) ? a[1] : a[0];
            a[0] = keep + __shfl_xor_sync(0xffffffffu, give, 4);
        }
        a[0] += __shfl_xor_sync(0xffffffffu, a[0], 2);
        a[0] += __shfl_xor_sync(0xffffffffu, a[0], 1);
        if (writer) gate_s[wrow] = a[0] + gcur;
        gcur = gnext;
        __syncthreads();

        float h = 0.f;
        if (pw) {
            int u = punit;
            float gi = gate_s[u], gf = gate_s[32 + u];
            float gg = gate_s[64 + u], go = gate_s[96 + u];
            c_reg = fsig(gf) * c_reg + fsig(gi) * ftanh(gg);
            h = fsig(go) * ftanh(c_reg);
            if (s < 1023) {
                // publish h to 2 peers: buf[par^1][unit] in ranks k2, k2+1
                unsigned int base = hb
                    + ((((unsigned)(par ^ 1)) << 8) + (unsigned)unit) * 4u;
                unsigned int ra;
                asm volatile("mapa.shared::cluster.u32 %0, %1, %2;"
                             : "=r"(ra) : "r"(base), "r"(k2));
                asm volatile("st.shared::cluster.f32 [%0], %1;"
                             :: "r"(ra), "f"(h) : "memory");
                asm volatile("mapa.shared::cluster.u32 %0, %1, %2;"
                             : "=r"(ra) : "r"(base), "r"(k2 + 1));
                asm volatile("st.shared::cluster.f32 [%0], %1;"
                             :: "r"(ra), "f"(h) : "memory");
            }
        }
        if (s < 1023) {
            // convergent arrive: releases pw warps' remote h stores; other
            // warps arrive with nothing outstanding. Peers' wait acquires.
            asm volatile("barrier.cluster.arrive.aligned;" ::: "memory");
        }
        // overlap the barrier with the global output store
        if (pw && lead) {
            yout[(size_t)pos * 512 + (dir << 8) + unit] = h;
            if (s == 1023) {
                d_hfin[layer * 512 + (dir << 8) + unit] = h;
                d_cfin[layer * 512 + (dir << 8) + unit] = c_reg;
            }
        }
    }
    cluster_bar();   // no CTA exits while peers could still touch its SMEM
}

// ----------------------- decoder recurrence (pipelined) --------------------
// 96 blocks x 512 threads. Blocks [0,32): cell0, 16 units each (64 gate rows
// x 512 cols). Blocks [32,96): cell1, 8 units each (32 gate rows x 1024 cols).
// Phase p: cell0 computes step p (p<64), cell1 computes step p-1 (p>=1).
__global__ void __launch_bounds__(512, 1) dec_recur_p(
    const float* __restrict__ dWih, const float* __restrict__ dWhh,
    const float* __restrict__ db)
{
    extern __shared__ float sm[];
    float* ws = sm;                    // 32768 floats (128KB)
    float* xc = sm + 32768;            // 1024
    float* gate_s = xc + 1024;         // 64

    int b = blockIdx.x, tid = threadIdx.x;
    int w = tid >> 5, l = tid & 31;

    if (b < 32) {
        // ---------------- cell 0 ----------------
        int ub = b * 16;
        for (int idx = tid; idx < 64 * 512; idx += 512) {
            int r = idx >> 9, k = idx & 511;
            int gr = (r >> 4) * 512 + ub + (r & 15);
            ws[idx] = dWhh[(size_t)gr * 512 + k];
        }
        float c0 = 0.f;
        if (tid < 16) {
            int ug = ub + tid;
            c0 = d_cfin[ug];
            d_h0g[ug] = d_hfin[ug];               // parity 0 init
        }
        __threadfence();
        grid_barrier(2, 96);

        bool writer = ((l & 7) == 0);
        int wrow = w * 4 + (l >> 3);
        int wgrow = (wrow >> 4) * 512 + ub + (wrow & 15);

        for (int p = 0; p < 65; p++) {
            int par = p & 1;
            if (p < 64) {
                float pre = 0.f;
                if (writer) pre = __ldcg(&d_DG0[(size_t)p * 2048 + wgrow]);
                xc[tid] = __ldcg(&d_h0g[par * 512 + tid]);
                __syncthreads();
                ulonglong2 xv[4];
#pragma unroll
                for (int q = 0; q < 4; q++)
                    xv[q] = *(const ulonglong2*)&xc[(q * 32 + l) * 4];
                float a[4];
#pragma unroll
                for (int r = 0; r < 4; r++) {
                    const float* wrp = &ws[(w * 4 + r) * 512];
                    unsigned long long acc = 0ull;
#pragma unroll
                    for (int q = 0; q < 4; q++) {
                        ulonglong2 wv = *(const ulonglong2*)&wrp[(q * 32 + l) * 4];
                        acc = fma2(wv.x, xv[q].x, acc);
                        acc = fma2(wv.y, xv[q].y, acc);
                    }
                    float lo, hi; unpack2(acc, lo, hi);
                    a[r] = lo + hi;
                }
#pragma unroll
                for (int i = 0; i < 2; i++) {
                    float give = (l & 16) ? a[i] : a[i + 2];
                    float keep = (l & 16) ? a[i + 2] : a[i];
                    a[i] = keep + __shfl_xor_sync(0xffffffffu, give, 16);
                }
                {
                    float give = (l & 8) ? a[0] : a[1];
                    float keep = (l & 8) ? a[1] : a[0];
                    a[0] = keep + __shfl_xor_sync(0xffffffffu, give, 8);
                }
                a[0] += __shfl_xor_sync(0xffffffffu, a[0], 4);
                a[0] += __shfl_xor_sync(0xffffffffu, a[0], 2);
                a[0] += __shfl_xor_sync(0xffffffffu, a[0], 1);
                if (writer) gate_s[wrow] = a[0] + pre;
                __syncthreads();
                if (tid < 16) {
                    int u = tid;
                    float gi = gate_s[u], gf = gate_s[16 + u];
                    float gg = gate_s[32 + u], go = gate_s[48 + u];
                    c0 = fsig(gf) * c0 + fsig(gi) * ftanh(gg);
                    float h = fsig(go) * ftanh(c0);
                    d_h0g[(par ^ 1) * 512 + ub + u] = h;
                }
            }
            __threadfence();
            grid_barrier(2, 96);
        }
    } else {
        // ---------------- cell 1 ----------------
        int bi = b - 32;
        int ub = bi * 8;
        for (int idx = tid; idx < 32 * 1024; idx += 512) {
            int r = idx >> 10, k = idx & 1023;
            int gr = (r >> 3) * 512 + ub + (r & 7);
            float v = (k < 512)
                ? dWih[(size_t)2048 * 512 + (size_t)gr * 512 + k]
                : dWhh[(size_t)2048 * 512 + (size_t)gr * 512 + (k - 512)];
            ws[r * 1024 + k] = v;
        }
        float c1 = 0.f;
        if (tid < 8) {
            int ug = ub + tid;
            c1 = d_cfin[512 + ug];
            d_h1g[512 + ug] = d_hfin[512 + ug];   // parity 1 init (first read p=1)
        }
        __threadfence();
        grid_barrier(2, 96);

        bool writer = ((l & 15) == 0);
        int wrow = w * 2 + (l >> 4);
        int wgrow = (wrow >> 3) * 512 + ub + (wrow & 7);
        float b1r = 0.f;
        if (writer) b1r = db[2048 + wgrow];

        for (int p = 0; p < 65; p++) {
            int par = p & 1;
            if (p >= 1) {
                int t = p - 1;
                xc[tid] = __ldcg(&d_h0g[par * 512 + tid]);
                xc[512 + tid] = __ldcg(&d_h1g[par * 512 + tid]);
                __syncthreads();
                ulonglong2 xv[8];
#pragma unroll
                for (int q = 0; q < 8; q++)
                    xv[q] = *(const ulonglong2*)&xc[(q * 32 + l) * 4];
                float a[2];
#pragma unroll
                for (int r = 0; r < 2; r++) {
                    const float* wrp = &ws[(w * 2 + r) * 1024];
                    unsigned long long acc = 0ull;
#pragma unroll
                    for (int q = 0; q < 8; q++) {
                        ulonglong2 wv = *(const ulonglong2*)&wrp[(q * 32 + l) * 4];
                        acc = fma2(wv.x, xv[q].x, acc);
                        acc = fma2(wv.y, xv[q].y, acc);
                    }
                    float lo, hi; unpack2(acc, lo, hi);
                    a[r] = lo + hi;
                }
                {
                    float give = (l & 16) ? a[0] : a[1];
                    float keep = (l & 16) ? a[1] : a[0];
                    a[0] = keep + __shfl_xor_sync(0xffffffffu, give, 16);
                }
                a[0] += __shfl_xor_sync(0xffffffffu, a[0], 8);
                a[0] += __shfl_xor_sync(0xffffffffu, a[0], 4);
                a[0] += __shfl_xor_sync(0xffffffffu, a[0], 2);
                a[0] += __shfl_xor_sync(0xffffffffu, a[0], 1);
                if (writer) gate_s[wrow] = a[0] + b1r;
                __syncthreads();
                if (tid < 8) {
                    int u = tid;
                    float gi = gate_s[u], gf = gate_s[8 + u];
                    float gg = gate_s[16 + u], go = gate_s[24 + u];
                    c1 = fsig(gf) * c1 + fsig(gi) * ftanh(gg);
                    float h = fsig(go) * ftanh(c1);
                    d_h1g[(par ^ 1) * 512 + ub + u] = h;
                    d_H2[(size_t)t * 512 + ub + u] = h;
                }
            }
            __threadfence();
            grid_barrier(2, 96);
        }
    }
}

// ------------------------------ scores -------------------------------------
__global__ void scores_kernel(const float* __restrict__ v,
                              const int* __restrict__ alens,
                              float* __restrict__ out)
{
    int t = blockIdx.x;
    int a = threadIdx.x >> 5;
    int lane = threadIdx.x & 31;
    const float* Kp = &d_Kenc[(size_t)(t * AA + a) * 256];
    const float* qp = &d_q[(size_t)t * 256];
    float s = 0.f;
#pragma unroll
    for (int i = 0; i < 8; i++) {
        int d = lane + (i << 5);
        s += tanhf(Kp[d] + qp[d]) * v[d];
    }
    s += __shfl_down_sync(0xffffffffu, s, 16);
    s += __shfl_down_sync(0xffffffffu, s, 8);
    s += __shfl_down_sync(0xffffffffu, s, 4);
    s += __shfl_down_sync(0xffffffffu, s, 2);
    s += __shfl_down_sync(0xffffffffu, s, 1);
    if (lane == 0) out[t * AA + a] = (a < alens[t]) ? s : -1e10f;
}

// ------------------------------ launcher -----------------------------------
extern "C" void kernel_launch(void* const* d_in, const int* in_sizes, int n_in,
                              void* d_out, int out_size)
{
    (void)in_sizes; (void)n_in; (void)out_size;
    const int*   lattice = (const int*)d_in[0];
    const int*   alens   = (const int*)d_in[1];
    const int*   inputs  = (const int*)d_in[2];
    const int*   gold    = (const int*)d_in[4];
    const int*   sos     = (const int*)d_in[5];
    const float* lat_tab = (const float*)d_in[6];
    const float* in_tab  = (const float*)d_in[7];
    const float* eWih0   = (const float*)d_in[8];
    const float* eWhh0   = (const float*)d_in[9];
    const float* eb0     = (const float*)d_in[10];
    const float* eWih1   = (const float*)d_in[11];
    const float* eWhh1   = (const float*)d_in[12];
    const float* eb1     = (const float*)d_in[13];
    const float* dWih    = (const float*)d_in[14];
    const float* dWhh    = (const float*)d_in[15];
    const float* db      = (const float*)d_in[16];
    const float* Wq      = (const float*)d_in[17];
    const float* Wk      = (const float*)d_in[18];
    const float* av      = (const float*)d_in[19];
    float* out = (float*)d_out;

    float *px, *py, *penc, *pG, *pK, *pdecin, *pDG0, *pH2, *pq;
    cudaGetSymbolAddress((void**)&px,    d_x);
    cudaGetSymbolAddress((void**)&py,    d_y);
    cudaGetSymbolAddress((void**)&penc,  d_enc);
    cudaGetSymbolAddress((void**)&pG,    d_G);
    cudaGetSymbolAddress((void**)&pK,    d_Kenc);
    cudaGetSymbolAddress((void**)&pdecin,d_decin);
    cudaGetSymbolAddress((void**)&pDG0,  d_DG0);
    cudaGetSymbolAddress((void**)&pH2,   d_H2);
    cudaGetSymbolAddress((void**)&pq,    d_q);

    const int DEC_SMEM = (32768 + 1024 + 64) * (int)sizeof(float);
    cudaFuncSetAttribute(dec_recur_p, cudaFuncAttributeMaxDynamicSharedMemorySize, DEC_SMEM);

    // 1. embeddings + decoder inputs
    embed_lattice<<<SEQ, 256>>>(lattice, lat_tab);
    build_decin<<<TT, 256>>>(inputs, gold, sos, lat_tab, in_tab);

    // 2. layer-0 gate preactivations
    gemm_tn128<<<dim3(8, 8, 2), 256>>>(px, eWih0, eb0, pG,
                                       SEQ, 1024, 256, 1024 * 256, SEQ * 1024, 1024);
    // 3. layer-0 recurrence (two independent 8-CTA clusters: fwd + bwd)
    enc_recur_cl<<<16, 512>>>(eWhh0, py, 0);
    // 4. layer-1 gate preactivations
    gemm_tn128<<<dim3(8, 8, 2), 256>>>(py, eWih1, eb1, pG,
                                       SEQ, 1024, 512, 1024 * 512, SEQ * 1024, 1024);
    // 5. layer-1 recurrence
    enc_recur_cl<<<16, 512>>>(eWhh1, penc, 1);
    // 6. attention keys + decoder layer-0 input preactivations
    gemm_nn<<<dim3(4, 16), 256>>>(penc, Wk, pK, SEQ, 256, 512);
    gemm_tn128<<<dim3(16, 1, 1), 256>>>(pdecin, dWih, db, pDG0,
                                        TT, 2048, 512, 0, 0, 0);
    // 7. decoder recurrence (pipelined: cell0 step t || cell1 step t-1)
    dec_recur_p<<<96, 512, DEC_SMEM>>>(dWih, dWhh, db);
    // 8. attention queries + scores
    gemm_nn<<<dim3(4, 1), 256>>>(pH2, Wq, pq, TT, 256, 512);
    scores_kernel<<<TT, 512>>>(av, alens, out);
}